// round 8
// baseline (speedup 1.0000x reference)
#include <cuda_runtime.h>
#include <cuda_fp16.h>

#define N_USER 100000
#define N_ITEM 200000
#define N_NODE 300000
#define LATDIM 64
#define E_INTER 4000000
#define E_SOC   2000000

// fp32 dense scratch
__device__ __align__(256) float g_soc   [4][(size_t)N_USER * LATDIM];
__device__ __align__(256) float g_inter [4][(size_t)N_NODE * LATDIM];
__device__ __align__(256) float g_fusedU[5][(size_t)N_USER * LATDIM];

// fp16 gather sources
// comb[k] = [ fp16(gate_k user rows) ; fp16(inter_{k} item rows) ]
__device__ __align__(256) __half g_comb[4][(size_t)N_NODE * LATDIM];
__device__ __align__(256) __half g_soch[3][(size_t)N_USER * LATDIM];

// CSR scratch. cnt arrays are self-resetting (zeroed by scan_final after use).
__device__ int  g_icnt[N_NODE];
__device__ int  g_icur[N_NODE];
__device__ int  g_iptr[N_NODE + 1];
__device__ __align__(16) int2 g_icv[E_INTER];
__device__ int  g_ibsum[256];

__device__ int  g_scnt[N_USER];
__device__ int  g_scur[N_USER];
__device__ int  g_sptr[N_USER + 1];
__device__ __align__(16) int2 g_scv[E_SOC];
__device__ int  g_sbsum[256];

// ---------------------------------------------------------------------------
// CSR build
// ---------------------------------------------------------------------------
__global__ void hist_rows(const int* __restrict__ rows, int E, int* __restrict__ cnt)
{
    int i = blockIdx.x * blockDim.x + threadIdx.x;
    if (i < E) atomicAdd(&cnt[rows[i]], 1);
}

__global__ void block_sum(const int* __restrict__ cnt, int N, int* __restrict__ bsum)
{
    __shared__ int sh[256];
    int base = blockIdx.x * 2048;
    int s = 0;
    for (int i = threadIdx.x; i < 2048; i += 256) {
        int idx = base + i;
        s += (idx < N) ? cnt[idx] : 0;
    }
    sh[threadIdx.x] = s;
    __syncthreads();
    for (int o = 128; o; o >>= 1) {
        if (threadIdx.x < o) sh[threadIdx.x] += sh[threadIdx.x + o];
        __syncthreads();
    }
    if (threadIdx.x == 0) bsum[blockIdx.x] = sh[0];
}

// Scans block sums locally, then the 2048-chunk; writes ptr & cur; resets cnt.
__global__ void scan_final(int* __restrict__ cnt, int N,
                           const int* __restrict__ bsum, int NB,
                           int* __restrict__ ptr, int* __restrict__ cur, int E)
{
    __shared__ int shb[256];
    __shared__ int sh[256];
    int t = threadIdx.x;

    shb[t] = (t < NB) ? bsum[t] : 0;
    __syncthreads();
    for (int o = 1; o < 256; o <<= 1) {
        int y = (t >= o) ? shb[t - o] : 0;
        __syncthreads();
        shb[t] += y;
        __syncthreads();
    }
    int block_off = (blockIdx.x == 0) ? 0 : shb[blockIdx.x - 1];

    int base = blockIdx.x * 2048 + t * 8;
    int loc[8];
    int s = 0;
    #pragma unroll
    for (int j = 0; j < 8; j++) {
        int idx = base + j;
        loc[j] = (idx < N) ? cnt[idx] : 0;
        if (idx < N) cnt[idx] = 0;           // self-reset for next call
        s += loc[j];
    }
    sh[t] = s;
    __syncthreads();
    for (int o = 1; o < 256; o <<= 1) {
        int y = (t >= o) ? sh[t - o] : 0;
        __syncthreads();
        sh[t] += y;
        __syncthreads();
    }
    int run = block_off + sh[t] - s;
    #pragma unroll
    for (int j = 0; j < 8; j++) {
        int idx = base + j;
        if (idx < N) { ptr[idx] = run; cur[idx] = run; run += loc[j]; }
    }
    if (blockIdx.x == 0 && t == 0) ptr[N] = E;
}

__global__ void scatter_edges(const int* __restrict__ rows, const int* __restrict__ cols,
                              const float* __restrict__ vals, int E,
                              int* __restrict__ cur, int2* __restrict__ cv)
{
    int i = blockIdx.x * blockDim.x + threadIdx.x;
    if (i >= E) return;
    int p = atomicAdd(&cur[rows[i]], 1);
    cv[p] = make_int2(cols[i], __float_as_int(vals[i]));
}

// scatter for inter graph fused with iE -> comb[0] item-region fp16 conversion
__global__ void scatter_conv(const int* __restrict__ rows, const int* __restrict__ cols,
                             const float* __restrict__ vals, int E,
                             int* __restrict__ cur, int2* __restrict__ cv,
                             const float2* __restrict__ iE2, __half2* __restrict__ dst2,
                             int nI2)
{
    int i = blockIdx.x * blockDim.x + threadIdx.x;
    if (i < E) {
        int p = atomicAdd(&cur[rows[i]], 1);
        cv[p] = make_int2(cols[i], __float_as_int(vals[i]));
    }
    if (i < nI2) dst2[i] = __float22half2_rn(iE2[i]);
}

// ---------------------------------------------------------------------------
// CSR SpMM v3: FULL WARP per row, uniform loop bounds (no divergence).
// Lane split: half = lane>>4 processes even/odd edges of the SAME row;
// each half gathers the full 128B fp16 row (16 lanes x 8B). Unroll 8 edges.
// Cross-half combine via shfl_xor(16); half0 stores fp32, half1 stores fp16.
// ---------------------------------------------------------------------------
__device__ __forceinline__ void acc_h(float4& acc, uint2 w, float v)
{
    float2 f0 = __half22float2(*reinterpret_cast<__half2*>(&w.x));
    float2 f1 = __half22float2(*reinterpret_cast<__half2*>(&w.y));
    acc.x += v * f0.x; acc.y += v * f0.y;
    acc.z += v * f1.x; acc.w += v * f1.y;
}

__global__ void __launch_bounds__(256) spmm_f16(
    const int* __restrict__ ptr, const int2* __restrict__ cv,
    const __half* __restrict__ src,
    float* __restrict__ dst, __half* __restrict__ dsth, int hmin, int nrows)
{
    int w = (blockIdx.x * blockDim.x + threadIdx.x) >> 5;   // warp id = row
    if (w >= nrows) return;
    int lane = threadIdx.x & 31;
    int half = lane >> 4;
    int q    = lane & 15;
    int s = __ldg(ptr + w);
    int e = __ldg(ptr + w + 1);
    float4 acc = make_float4(0.f, 0.f, 0.f, 0.f);

    int i = s;
    for (; i + 8 <= e; i += 8) {
        int2 a0 = __ldg(cv + i     + half);
        int2 a1 = __ldg(cv + i + 2 + half);
        int2 a2 = __ldg(cv + i + 4 + half);
        int2 a3 = __ldg(cv + i + 6 + half);
        uint2 w0 = __ldg((const uint2*)(src + (size_t)a0.x * LATDIM) + q);
        uint2 w1 = __ldg((const uint2*)(src + (size_t)a1.x * LATDIM) + q);
        uint2 w2 = __ldg((const uint2*)(src + (size_t)a2.x * LATDIM) + q);
        uint2 w3 = __ldg((const uint2*)(src + (size_t)a3.x * LATDIM) + q);
        acc_h(acc, w0, __int_as_float(a0.y));
        acc_h(acc, w1, __int_as_float(a1.y));
        acc_h(acc, w2, __int_as_float(a2.y));
        acc_h(acc, w3, __int_as_float(a3.y));
    }
    for (; i + 2 <= e; i += 2) {
        int2 a = __ldg(cv + i + half);
        uint2 wv = __ldg((const uint2*)(src + (size_t)a.x * LATDIM) + q);
        acc_h(acc, wv, __int_as_float(a.y));
    }
    if (i < e && half == 0) {               // odd tail edge: half 0 only
        int2 a = __ldg(cv + i);
        uint2 wv = __ldg((const uint2*)(src + (size_t)a.x * LATDIM) + q);
        acc_h(acc, wv, __int_as_float(a.y));
    }

    // combine halves
    acc.x += __shfl_xor_sync(0xffffffffu, acc.x, 16);
    acc.y += __shfl_xor_sync(0xffffffffu, acc.y, 16);
    acc.z += __shfl_xor_sync(0xffffffffu, acc.z, 16);
    acc.w += __shfl_xor_sync(0xffffffffu, acc.w, 16);

    if (half == 0) {
        ((float4*)(dst + (size_t)w * LATDIM))[q] = acc;
    } else if (dsth != nullptr && w >= hmin) {
        __half2 h0 = __floats2half2_rn(acc.x, acc.y);
        __half2 h1 = __floats2half2_rn(acc.z, acc.w);
        uint2 pk;
        pk.x = *reinterpret_cast<unsigned*>(&h0);
        pk.y = *reinterpret_cast<unsigned*>(&h1);
        ((uint2*)(dsth + (size_t)w * LATDIM))[q] = pk;
    }
}

// fp32-source variant (soc layer 0 only, gathering uE directly).
// Same structure; each half gathers the 256B fp32 row (16 lanes x 16B).
__global__ void __launch_bounds__(256) spmm_f32src(
    const int* __restrict__ ptr, const int2* __restrict__ cv,
    const float* __restrict__ src,
    float* __restrict__ dst, __half* __restrict__ dsth, int hmin, int nrows)
{
    int w = (blockIdx.x * blockDim.x + threadIdx.x) >> 5;
    if (w >= nrows) return;
    int lane = threadIdx.x & 31;
    int half = lane >> 4;
    int q    = lane & 15;
    int s = __ldg(ptr + w);
    int e = __ldg(ptr + w + 1);
    float4 acc = make_float4(0.f, 0.f, 0.f, 0.f);

    int i = s;
    for (; i + 8 <= e; i += 8) {
        int2 a0 = __ldg(cv + i     + half);
        int2 a1 = __ldg(cv + i + 2 + half);
        int2 a2 = __ldg(cv + i + 4 + half);
        int2 a3 = __ldg(cv + i + 6 + half);
        float4 x0 = __ldg((const float4*)(src + (size_t)a0.x * LATDIM) + q);
        float4 x1 = __ldg((const float4*)(src + (size_t)a1.x * LATDIM) + q);
        float4 x2 = __ldg((const float4*)(src + (size_t)a2.x * LATDIM) + q);
        float4 x3 = __ldg((const float4*)(src + (size_t)a3.x * LATDIM) + q);
        float v0 = __int_as_float(a0.y), v1 = __int_as_float(a1.y);
        float v2 = __int_as_float(a2.y), v3 = __int_as_float(a3.y);
        acc.x += v0 * x0.x; acc.y += v0 * x0.y; acc.z += v0 * x0.z; acc.w += v0 * x0.w;
        acc.x += v1 * x1.x; acc.y += v1 * x1.y; acc.z += v1 * x1.z; acc.w += v1 * x1.w;
        acc.x += v2 * x2.x; acc.y += v2 * x2.y; acc.z += v2 * x2.z; acc.w += v2 * x2.w;
        acc.x += v3 * x3.x; acc.y += v3 * x3.y; acc.z += v3 * x3.z; acc.w += v3 * x3.w;
    }
    for (; i + 2 <= e; i += 2) {
        int2 a = __ldg(cv + i + half);
        float4 x = __ldg((const float4*)(src + (size_t)a.x * LATDIM) + q);
        float v = __int_as_float(a.y);
        acc.x += v * x.x; acc.y += v * x.y; acc.z += v * x.z; acc.w += v * x.w;
    }
    if (i < e && half == 0) {
        int2 a = __ldg(cv + i);
        float4 x = __ldg((const float4*)(src + (size_t)a.x * LATDIM) + q);
        float v = __int_as_float(a.y);
        acc.x += v * x.x; acc.y += v * x.y; acc.z += v * x.z; acc.w += v * x.w;
    }

    acc.x += __shfl_xor_sync(0xffffffffu, acc.x, 16);
    acc.y += __shfl_xor_sync(0xffffffffu, acc.y, 16);
    acc.z += __shfl_xor_sync(0xffffffffu, acc.z, 16);
    acc.w += __shfl_xor_sync(0xffffffffu, acc.w, 16);

    if (half == 0) {
        ((float4*)(dst + (size_t)w * LATDIM))[q] = acc;
    } else if (dsth != nullptr && w >= hmin) {
        __half2 h0 = __floats2half2_rn(acc.x, acc.y);
        __half2 h1 = __floats2half2_rn(acc.z, acc.w);
        uint2 pk;
        pk.x = *reinterpret_cast<unsigned*>(&h0);
        pk.y = *reinterpret_cast<unsigned*>(&h1);
        ((uint2*)(dsth + (size_t)w * LATDIM))[q] = pk;
    }
}

// ---------------------------------------------------------------------------
// Gate + fuse (fp32 in, fp32 out + optional fp16 out into comb user region)
// ---------------------------------------------------------------------------
__global__ void gate_fuse(const float* __restrict__ uu, const float* __restrict__ hi,
                          const float* __restrict__ Wg, const float* __restrict__ bg,
                          float* __restrict__ out, __half* __restrict__ outh)
{
    int gt = blockIdx.x * blockDim.x + threadIdx.x;
    int u = gt >> 5;
    int lane = threadIdx.x & 31;
    if (u >= N_USER) return;

    float2 za = ((const float2*)(uu + (size_t)u * LATDIM))[lane];
    float2 ha = ((const float2*)(hi + (size_t)u * LATDIM))[lane];

    int d = 2 * lane;
    float p0 = za.x * Wg[d]       + za.y * Wg[d + 1]
             + ha.x * Wg[64 + d]  + ha.y * Wg[64 + d + 1];
    float p1 = za.x * Wg[128 + d]      + za.y * Wg[128 + d + 1]
             + ha.x * Wg[128 + 64 + d] + ha.y * Wg[128 + 64 + d + 1];
    #pragma unroll
    for (int o = 16; o; o >>= 1) {
        p0 += __shfl_xor_sync(0xffffffffu, p0, o);
        p1 += __shfl_xor_sync(0xffffffffu, p1, o);
    }
    float l0 = p0 + bg[0];
    float l1 = p1 + bg[1];
    l0 = l0 > 0.f ? l0 : 0.01f * l0;
    l1 = l1 > 0.f ? l1 : 0.01f * l1;
    float mx = fmaxf(l0, l1);
    float e0 = __expf(l0 - mx), e1 = __expf(l1 - mx);
    float inv = 1.f / (e0 + e1);
    float m0 = e0 * inv, m1 = e1 * inv;

    float2 o2 = make_float2(za.x * m0 + ha.x * m1, za.y * m0 + ha.y * m1);
    ((float2*)(out + (size_t)u * LATDIM))[lane] = o2;
    if (outh != nullptr)
        ((__half2*)(outh + (size_t)u * LATDIM))[lane] = __float22half2_rn(o2);
}

// ---------------------------------------------------------------------------
// 5-way attention readout
// ---------------------------------------------------------------------------
__global__ void attn5(const float* __restrict__ f0, const float* __restrict__ f1,
                      const float* __restrict__ f2, const float* __restrict__ f3,
                      const float* __restrict__ f4,
                      const float* __restrict__ W, const float* __restrict__ b,
                      float* __restrict__ out, int N)
{
    __shared__ float sW[5 * 320];
    __shared__ float sb[5];
    for (int i = threadIdx.x; i < 5 * 320; i += blockDim.x) sW[i] = W[i];
    if (threadIdx.x < 5) sb[threadIdx.x] = b[threadIdx.x];
    __syncthreads();

    int gt = blockIdx.x * blockDim.x + threadIdx.x;
    int u = gt >> 5;
    int lane = threadIdx.x & 31;
    if (u >= N) return;

    const float* fp[5] = {f0, f1, f2, f3, f4};
    float2 f[5];
    #pragma unroll
    for (int k = 0; k < 5; k++)
        f[k] = ((const float2*)(fp[k] + (size_t)u * LATDIM))[lane];

    int d = 2 * lane;
    float p[5];
    #pragma unroll
    for (int j = 0; j < 5; j++) {
        float acc = 0.f;
        #pragma unroll
        for (int k = 0; k < 5; k++) {
            acc += f[k].x * sW[j * 320 + k * 64 + d];
            acc += f[k].y * sW[j * 320 + k * 64 + d + 1];
        }
        p[j] = acc;
    }
    #pragma unroll
    for (int j = 0; j < 5; j++)
        #pragma unroll
        for (int o = 16; o; o >>= 1)
            p[j] += __shfl_xor_sync(0xffffffffu, p[j], o);

    float mx = -1e30f;
    #pragma unroll
    for (int j = 0; j < 5; j++) {
        float l = p[j] + sb[j];
        l = l > 0.f ? l : 0.01f * l;
        p[j] = l;
        mx = fmaxf(mx, l);
    }
    float se = 0.f;
    #pragma unroll
    for (int j = 0; j < 5; j++) { p[j] = __expf(p[j] - mx); se += p[j]; }
    float inv = 1.f / se;

    float2 o2 = make_float2(0.f, 0.f);
    #pragma unroll
    for (int k = 0; k < 5; k++) {
        float w = p[k] * inv;
        o2.x += w * f[k].x;
        o2.y += w * f[k].y;
    }
    ((float2*)(out + (size_t)u * LATDIM))[lane] = o2;
}

// ---------------------------------------------------------------------------

extern "C" void kernel_launch(void* const* d_in, const int* in_sizes, int n_in,
                              void* d_out, int out_size)
{
    const float* uE  = (const float*)d_in[0];
    const float* iE  = (const float*)d_in[1];
    const float* Wg  = (const float*)d_in[2];
    const float* bg  = (const float*)d_in[3];
    const float* WL1 = (const float*)d_in[4];
    const float* bL1 = (const float*)d_in[5];
    const float* WL2 = (const float*)d_in[6];
    const float* bL2 = (const float*)d_in[7];
    const int*   ir  = (const int*)d_in[8];
    const int*   ic  = (const int*)d_in[9];
    const float* iv  = (const float*)d_in[10];
    const int*   sr  = (const int*)d_in[11];
    const int*   sc  = (const int*)d_in[12];
    const float* sv  = (const float*)d_in[13];
    float* out = (float*)d_out;

    float *socB, *intB, *fuB;
    __half *combB, *socH;
    cudaGetSymbolAddress((void**)&socB,  g_soc);
    cudaGetSymbolAddress((void**)&intB,  g_inter);
    cudaGetSymbolAddress((void**)&fuB,   g_fusedU);
    cudaGetSymbolAddress((void**)&combB, g_comb);
    cudaGetSymbolAddress((void**)&socH,  g_soch);

    int *icnt, *icur, *iptr, *ibs, *scnt, *scur, *sptr, *sbs;
    int2 *icv, *scv;
    cudaGetSymbolAddress((void**)&icnt, g_icnt);
    cudaGetSymbolAddress((void**)&icur, g_icur);
    cudaGetSymbolAddress((void**)&iptr, g_iptr);
    cudaGetSymbolAddress((void**)&icv,  g_icv);
    cudaGetSymbolAddress((void**)&ibs,  g_ibsum);
    cudaGetSymbolAddress((void**)&scnt, g_scnt);
    cudaGetSymbolAddress((void**)&scur, g_scur);
    cudaGetSymbolAddress((void**)&sptr, g_sptr);
    cudaGetSymbolAddress((void**)&scv,  g_scv);
    cudaGetSymbolAddress((void**)&sbs,  g_sbsum);

    const size_t USZ = (size_t)N_USER * LATDIM;
    const size_t NSZ = (size_t)N_NODE * LATDIM;
    const int NB_I = (N_NODE + 2047) / 2048;   // 147
    const int NB_S = (N_USER + 2047) / 2048;   // 49
    const int nI2 = N_ITEM * LATDIM / 2;       // 6.4M half2

    // --- soc CSR build (cnt arrays pre-zeroed: static init / self-reset) ---
    hist_rows<<<(E_SOC + 255) / 256, 256>>>(sr, E_SOC, scnt);
    block_sum<<<NB_S, 256>>>(scnt, N_USER, sbs);
    scan_final<<<NB_S, 256>>>(scnt, N_USER, sbs, NB_S, sptr, scur, E_SOC);
    scatter_edges<<<(E_SOC + 255) / 256, 256>>>(sr, sc, sv, E_SOC, scur, scv);

    // --- soc layer 1 ---
    spmm_f32src<<<(N_USER * 32 + 255) / 256, 256>>>(sptr, scv, uE,
                                                    socB, socH, 0, N_USER);

    // --- inter CSR build (+ iE -> comb[0] item region fp16) ---
    hist_rows<<<(E_INTER + 255) / 256, 256>>>(ir, E_INTER, icnt);
    block_sum<<<NB_I, 256>>>(icnt, N_NODE, ibs);
    scan_final<<<NB_I, 256>>>(icnt, N_NODE, ibs, NB_I, iptr, icur, E_INTER);
    {
        int tot = (E_INTER > nI2) ? E_INTER : nI2;
        scatter_conv<<<(tot + 255) / 256, 256>>>(ir, ic, iv, E_INTER, icur, icv,
                                                 (const float2*)iE,
                                                 (__half2*)(combB + USZ), nI2);
    }

    // --- soc layers 2..4 ---
    for (int k = 1; k < 4; k++) {
        spmm_f16<<<(N_USER * 32 + 255) / 256, 256>>>(
            sptr, scv, socH + (size_t)(k - 1) * USZ,
            socB + (size_t)k * USZ,
            (k < 3) ? socH + (size_t)k * USZ : nullptr, 0, N_USER);
    }

    // --- fused layers 0..4 (layer-5 interaction spmm is dead code) ---
    for (int k = 0; k < 5; k++) {
        const float* uu  = (k == 0) ? uE : socB + (size_t)(k - 1) * USZ;
        const float* hiU = (k == 0) ? uE : intB + (size_t)(k - 1) * NSZ;
        float* fU = fuB + (size_t)k * USZ;
        __half* combk = combB + (size_t)k * NSZ;

        gate_fuse<<<(N_USER * 32 + 255) / 256, 256>>>(
            uu, hiU, Wg + k * 256, bg + k * 2, fU,
            (k < 4) ? combk : nullptr);

        if (k < 4) {
            // spmm k: source comb[k]; fp32 all rows -> intB[k];
            // fp16 item rows -> comb[k+1] item region (k<3)
            spmm_f16<<<(N_NODE * 32 + 255) / 256, 256>>>(
                iptr, icv, combk,
                intB + (size_t)k * NSZ,
                (k < 3) ? combB + (size_t)(k + 1) * NSZ : nullptr,
                N_USER, N_NODE);
        }
    }

    // --- attention readouts ---
    attn5<<<(N_USER * 32 + 255) / 256, 256>>>(
        fuB, fuB + USZ, fuB + 2 * USZ, fuB + 3 * USZ, fuB + 4 * USZ,
        WL1, bL1, out, N_USER);
    attn5<<<(N_ITEM * 32 + 255) / 256, 256>>>(
        iE,
        intB + 0 * NSZ + USZ, intB + 1 * NSZ + USZ,
        intB + 2 * NSZ + USZ, intB + 3 * NSZ + USZ,
        WL2, bL2, out + USZ, N_ITEM);
}

// round 9
// speedup vs baseline: 1.1052x; 1.1052x over previous
#include <cuda_runtime.h>
#include <cuda_fp16.h>

#define N_USER 100000
#define N_ITEM 200000
#define N_NODE 300000
#define LATDIM 64
#define E_INTER 4000000
#define E_SOC   2000000

// fp32 dense scratch
__device__ __align__(256) float g_soc   [4][(size_t)N_USER * LATDIM];
__device__ __align__(256) float g_inter [4][(size_t)N_NODE * LATDIM];
__device__ __align__(256) float g_fusedU[5][(size_t)N_USER * LATDIM];

// fp16 gather sources
// comb[k] = [ fp16(gate_k user rows) ; fp16(inter_{k} item rows) ]
__device__ __align__(256) __half g_comb[4][(size_t)N_NODE * LATDIM];
__device__ __align__(256) __half g_soch[3][(size_t)N_USER * LATDIM];

// CSR scratch. cnt arrays are self-resetting (zeroed by scan_final after use).
__device__ int  g_icnt[N_NODE];
__device__ int  g_icur[N_NODE];
__device__ int  g_iptr[N_NODE + 1];
__device__ __align__(16) int2 g_icv[E_INTER];
__device__ int  g_ibsum[256];

__device__ int  g_scnt[N_USER];
__device__ int  g_scur[N_USER];
__device__ int  g_sptr[N_USER + 1];
__device__ __align__(16) int2 g_scv[E_SOC];
__device__ int  g_sbsum[256];

// ---------------------------------------------------------------------------
// CSR build
// ---------------------------------------------------------------------------
__global__ void hist_rows(const int* __restrict__ rows, int E, int* __restrict__ cnt)
{
    int i = blockIdx.x * blockDim.x + threadIdx.x;
    if (i < E) atomicAdd(&cnt[rows[i]], 1);
}

__global__ void block_sum(const int* __restrict__ cnt, int N, int* __restrict__ bsum)
{
    __shared__ int sh[256];
    int base = blockIdx.x * 2048;
    int s = 0;
    for (int i = threadIdx.x; i < 2048; i += 256) {
        int idx = base + i;
        s += (idx < N) ? cnt[idx] : 0;
    }
    sh[threadIdx.x] = s;
    __syncthreads();
    for (int o = 128; o; o >>= 1) {
        if (threadIdx.x < o) sh[threadIdx.x] += sh[threadIdx.x + o];
        __syncthreads();
    }
    if (threadIdx.x == 0) bsum[blockIdx.x] = sh[0];
}

// Scans block sums locally, then the 2048-chunk; writes ptr & cur; resets cnt.
__global__ void scan_final(int* __restrict__ cnt, int N,
                           const int* __restrict__ bsum, int NB,
                           int* __restrict__ ptr, int* __restrict__ cur, int E)
{
    __shared__ int shb[256];
    __shared__ int sh[256];
    int t = threadIdx.x;

    shb[t] = (t < NB) ? bsum[t] : 0;
    __syncthreads();
    for (int o = 1; o < 256; o <<= 1) {
        int y = (t >= o) ? shb[t - o] : 0;
        __syncthreads();
        shb[t] += y;
        __syncthreads();
    }
    int block_off = (blockIdx.x == 0) ? 0 : shb[blockIdx.x - 1];

    int base = blockIdx.x * 2048 + t * 8;
    int loc[8];
    int s = 0;
    #pragma unroll
    for (int j = 0; j < 8; j++) {
        int idx = base + j;
        loc[j] = (idx < N) ? cnt[idx] : 0;
        if (idx < N) cnt[idx] = 0;           // self-reset for next call
        s += loc[j];
    }
    sh[t] = s;
    __syncthreads();
    for (int o = 1; o < 256; o <<= 1) {
        int y = (t >= o) ? sh[t - o] : 0;
        __syncthreads();
        sh[t] += y;
        __syncthreads();
    }
    int run = block_off + sh[t] - s;
    #pragma unroll
    for (int j = 0; j < 8; j++) {
        int idx = base + j;
        if (idx < N) { ptr[idx] = run; cur[idx] = run; run += loc[j]; }
    }
    if (blockIdx.x == 0 && t == 0) ptr[N] = E;
}

__global__ void scatter_edges(const int* __restrict__ rows, const int* __restrict__ cols,
                              const float* __restrict__ vals, int E,
                              int* __restrict__ cur, int2* __restrict__ cv)
{
    int i = blockIdx.x * blockDim.x + threadIdx.x;
    if (i >= E) return;
    int p = atomicAdd(&cur[rows[i]], 1);
    cv[p] = make_int2(cols[i], __float_as_int(vals[i]));
}

// scatter for inter graph fused with iE -> comb[0] item-region fp16 conversion
__global__ void scatter_conv(const int* __restrict__ rows, const int* __restrict__ cols,
                             const float* __restrict__ vals, int E,
                             int* __restrict__ cur, int2* __restrict__ cv,
                             const float2* __restrict__ iE2, __half2* __restrict__ dst2,
                             int nI2)
{
    int i = blockIdx.x * blockDim.x + threadIdx.x;
    if (i < E) {
        int p = atomicAdd(&cur[rows[i]], 1);
        cv[p] = make_int2(cols[i], __float_as_int(vals[i]));
    }
    if (i < nI2) dst2[i] = __float22half2_rn(iE2[i]);
}

// ---------------------------------------------------------------------------
// CSR SpMM (R7 best): HALF-WARP per row, fp16 source, 8B per lane.
// Edge stream as uint4 (2 packed edges / LDG.128), unrolled x8.
// fp32 accumulate; fp32 store + optional fp16 store for rows >= hmin.
// ---------------------------------------------------------------------------
__device__ __forceinline__ void acc_h(float4& acc, uint2 w, float v)
{
    float2 f0 = __half22float2(*reinterpret_cast<__half2*>(&w.x));
    float2 f1 = __half22float2(*reinterpret_cast<__half2*>(&w.y));
    acc.x += v * f0.x; acc.y += v * f0.y;
    acc.z += v * f1.x; acc.w += v * f1.y;
}

__device__ __forceinline__ void store_row(float4 acc, float* dst, __half* dsth,
                                          int hmin, int hw, int q)
{
    ((float4*)(dst + (size_t)hw * LATDIM))[q] = acc;
    if (dsth != nullptr && hw >= hmin) {
        __half2 h0 = __floats2half2_rn(acc.x, acc.y);
        __half2 h1 = __floats2half2_rn(acc.z, acc.w);
        uint2 pk;
        pk.x = *reinterpret_cast<unsigned*>(&h0);
        pk.y = *reinterpret_cast<unsigned*>(&h1);
        ((uint2*)(dsth + (size_t)hw * LATDIM))[q] = pk;
    }
}

__global__ void __launch_bounds__(256) spmm_f16(
    const int* __restrict__ ptr, const int2* __restrict__ cv,
    const __half* __restrict__ src,
    float* __restrict__ dst, __half* __restrict__ dsth, int hmin, int nrows)
{
    int hw = (blockIdx.x * blockDim.x + threadIdx.x) >> 4;
    int q  = threadIdx.x & 15;
    if (hw >= nrows) return;
    int s = __ldg(ptr + hw);
    int e = __ldg(ptr + hw + 1);
    float4 acc = make_float4(0.f, 0.f, 0.f, 0.f);
    int i = s;
    if ((i & 1) && i < e) {
        int2 a = __ldg(cv + i);
        uint2 w = __ldg((const uint2*)(src + (size_t)a.x * LATDIM) + q);
        acc_h(acc, w, __int_as_float(a.y));
        i++;
    }
    const uint4* cv4 = (const uint4*)cv;
    for (; i + 8 <= e; i += 8) {
        int b = i >> 1;
        uint4 p0 = __ldg(cv4 + b);
        uint4 p1 = __ldg(cv4 + b + 1);
        uint4 p2 = __ldg(cv4 + b + 2);
        uint4 p3 = __ldg(cv4 + b + 3);
        uint2 w0 = __ldg((const uint2*)(src + (size_t)p0.x * LATDIM) + q);
        uint2 w1 = __ldg((const uint2*)(src + (size_t)p0.z * LATDIM) + q);
        uint2 w2 = __ldg((const uint2*)(src + (size_t)p1.x * LATDIM) + q);
        uint2 w3 = __ldg((const uint2*)(src + (size_t)p1.z * LATDIM) + q);
        uint2 w4 = __ldg((const uint2*)(src + (size_t)p2.x * LATDIM) + q);
        uint2 w5 = __ldg((const uint2*)(src + (size_t)p2.z * LATDIM) + q);
        uint2 w6 = __ldg((const uint2*)(src + (size_t)p3.x * LATDIM) + q);
        uint2 w7 = __ldg((const uint2*)(src + (size_t)p3.z * LATDIM) + q);
        acc_h(acc, w0, __uint_as_float(p0.y));
        acc_h(acc, w1, __uint_as_float(p0.w));
        acc_h(acc, w2, __uint_as_float(p1.y));
        acc_h(acc, w3, __uint_as_float(p1.w));
        acc_h(acc, w4, __uint_as_float(p2.y));
        acc_h(acc, w5, __uint_as_float(p2.w));
        acc_h(acc, w6, __uint_as_float(p3.y));
        acc_h(acc, w7, __uint_as_float(p3.w));
    }
    for (; i + 2 <= e; i += 2) {
        uint4 p = __ldg(cv4 + (i >> 1));
        uint2 w0 = __ldg((const uint2*)(src + (size_t)p.x * LATDIM) + q);
        uint2 w1 = __ldg((const uint2*)(src + (size_t)p.z * LATDIM) + q);
        acc_h(acc, w0, __uint_as_float(p.y));
        acc_h(acc, w1, __uint_as_float(p.w));
    }
    if (i < e) {
        int2 a = __ldg(cv + i);
        uint2 w = __ldg((const uint2*)(src + (size_t)a.x * LATDIM) + q);
        acc_h(acc, w, __int_as_float(a.y));
    }
    store_row(acc, dst, dsth, hmin, hw, q);
}

// fp32-source variant (only soc layer 0, gathering uE directly)
__global__ void __launch_bounds__(256) spmm_f32src(
    const int* __restrict__ ptr, const int2* __restrict__ cv,
    const float* __restrict__ src,
    float* __restrict__ dst, __half* __restrict__ dsth, int hmin, int nrows)
{
    int hw = (blockIdx.x * blockDim.x + threadIdx.x) >> 4;
    int q  = threadIdx.x & 15;
    if (hw >= nrows) return;
    int s = __ldg(ptr + hw);
    int e = __ldg(ptr + hw + 1);
    float4 acc = make_float4(0.f, 0.f, 0.f, 0.f);
    int i = s;
    if ((i & 1) && i < e) {
        int2 a = __ldg(cv + i);
        float4 x = __ldg((const float4*)(src + (size_t)a.x * LATDIM) + q);
        float v = __int_as_float(a.y);
        acc.x += v * x.x; acc.y += v * x.y; acc.z += v * x.z; acc.w += v * x.w;
        i++;
    }
    const uint4* cv4 = (const uint4*)cv;
    for (; i + 4 <= e; i += 4) {
        int b = i >> 1;
        uint4 p0 = __ldg(cv4 + b);
        uint4 p1 = __ldg(cv4 + b + 1);
        float4 x0 = __ldg((const float4*)(src + (size_t)p0.x * LATDIM) + q);
        float4 x1 = __ldg((const float4*)(src + (size_t)p0.z * LATDIM) + q);
        float4 x2 = __ldg((const float4*)(src + (size_t)p1.x * LATDIM) + q);
        float4 x3 = __ldg((const float4*)(src + (size_t)p1.z * LATDIM) + q);
        float v0 = __uint_as_float(p0.y), v1 = __uint_as_float(p0.w);
        float v2 = __uint_as_float(p1.y), v3 = __uint_as_float(p1.w);
        acc.x += v0 * x0.x; acc.y += v0 * x0.y; acc.z += v0 * x0.z; acc.w += v0 * x0.w;
        acc.x += v1 * x1.x; acc.y += v1 * x1.y; acc.z += v1 * x1.z; acc.w += v1 * x1.w;
        acc.x += v2 * x2.x; acc.y += v2 * x2.y; acc.z += v2 * x2.z; acc.w += v2 * x2.w;
        acc.x += v3 * x3.x; acc.y += v3 * x3.y; acc.z += v3 * x3.z; acc.w += v3 * x3.w;
    }
    for (; i < e; i++) {
        int2 a = __ldg(cv + i);
        float4 x = __ldg((const float4*)(src + (size_t)a.x * LATDIM) + q);
        float v = __int_as_float(a.y);
        acc.x += v * x.x; acc.y += v * x.y; acc.z += v * x.z; acc.w += v * x.w;
    }
    store_row(acc, dst, dsth, hmin, hw, q);
}

// ---------------------------------------------------------------------------
// Gate + fuse (fp32 in, fp32 out + optional fp16 out into comb user region)
// ---------------------------------------------------------------------------
__global__ void gate_fuse(const float* __restrict__ uu, const float* __restrict__ hi,
                          const float* __restrict__ Wg, const float* __restrict__ bg,
                          float* __restrict__ out, __half* __restrict__ outh)
{
    int gt = blockIdx.x * blockDim.x + threadIdx.x;
    int u = gt >> 5;
    int lane = threadIdx.x & 31;
    if (u >= N_USER) return;

    float2 za = ((const float2*)(uu + (size_t)u * LATDIM))[lane];
    float2 ha = ((const float2*)(hi + (size_t)u * LATDIM))[lane];

    int d = 2 * lane;
    float p0 = za.x * Wg[d]       + za.y * Wg[d + 1]
             + ha.x * Wg[64 + d]  + ha.y * Wg[64 + d + 1];
    float p1 = za.x * Wg[128 + d]      + za.y * Wg[128 + d + 1]
             + ha.x * Wg[128 + 64 + d] + ha.y * Wg[128 + 64 + d + 1];
    #pragma unroll
    for (int o = 16; o; o >>= 1) {
        p0 += __shfl_xor_sync(0xffffffffu, p0, o);
        p1 += __shfl_xor_sync(0xffffffffu, p1, o);
    }
    float l0 = p0 + bg[0];
    float l1 = p1 + bg[1];
    l0 = l0 > 0.f ? l0 : 0.01f * l0;
    l1 = l1 > 0.f ? l1 : 0.01f * l1;
    float mx = fmaxf(l0, l1);
    float e0 = __expf(l0 - mx), e1 = __expf(l1 - mx);
    float inv = 1.f / (e0 + e1);
    float m0 = e0 * inv, m1 = e1 * inv;

    float2 o2 = make_float2(za.x * m0 + ha.x * m1, za.y * m0 + ha.y * m1);
    ((float2*)(out + (size_t)u * LATDIM))[lane] = o2;
    if (outh != nullptr)
        ((__half2*)(outh + (size_t)u * LATDIM))[lane] = __float22half2_rn(o2);
}

// ---------------------------------------------------------------------------
// 5-way attention readout
// ---------------------------------------------------------------------------
__global__ void attn5(const float* __restrict__ f0, const float* __restrict__ f1,
                      const float* __restrict__ f2, const float* __restrict__ f3,
                      const float* __restrict__ f4,
                      const float* __restrict__ W, const float* __restrict__ b,
                      float* __restrict__ out, int N)
{
    __shared__ float sW[5 * 320];
    __shared__ float sb[5];
    for (int i = threadIdx.x; i < 5 * 320; i += blockDim.x) sW[i] = W[i];
    if (threadIdx.x < 5) sb[threadIdx.x] = b[threadIdx.x];
    __syncthreads();

    int gt = blockIdx.x * blockDim.x + threadIdx.x;
    int u = gt >> 5;
    int lane = threadIdx.x & 31;
    if (u >= N) return;

    const float* fp[5] = {f0, f1, f2, f3, f4};
    float2 f[5];
    #pragma unroll
    for (int k = 0; k < 5; k++)
        f[k] = ((const float2*)(fp[k] + (size_t)u * LATDIM))[lane];

    int d = 2 * lane;
    float p[5];
    #pragma unroll
    for (int j = 0; j < 5; j++) {
        float acc = 0.f;
        #pragma unroll
        for (int k = 0; k < 5; k++) {
            acc += f[k].x * sW[j * 320 + k * 64 + d];
            acc += f[k].y * sW[j * 320 + k * 64 + d + 1];
        }
        p[j] = acc;
    }
    #pragma unroll
    for (int j = 0; j < 5; j++)
        #pragma unroll
        for (int o = 16; o; o >>= 1)
            p[j] += __shfl_xor_sync(0xffffffffu, p[j], o);

    float mx = -1e30f;
    #pragma unroll
    for (int j = 0; j < 5; j++) {
        float l = p[j] + sb[j];
        l = l > 0.f ? l : 0.01f * l;
        p[j] = l;
        mx = fmaxf(mx, l);
    }
    float se = 0.f;
    #pragma unroll
    for (int j = 0; j < 5; j++) { p[j] = __expf(p[j] - mx); se += p[j]; }
    float inv = 1.f / se;

    float2 o2 = make_float2(0.f, 0.f);
    #pragma unroll
    for (int k = 0; k < 5; k++) {
        float w = p[k] * inv;
        o2.x += w * f[k].x;
        o2.y += w * f[k].y;
    }
    ((float2*)(out + (size_t)u * LATDIM))[lane] = o2;
}

// ---------------------------------------------------------------------------

extern "C" void kernel_launch(void* const* d_in, const int* in_sizes, int n_in,
                              void* d_out, int out_size)
{
    const float* uE  = (const float*)d_in[0];
    const float* iE  = (const float*)d_in[1];
    const float* Wg  = (const float*)d_in[2];
    const float* bg  = (const float*)d_in[3];
    const float* WL1 = (const float*)d_in[4];
    const float* bL1 = (const float*)d_in[5];
    const float* WL2 = (const float*)d_in[6];
    const float* bL2 = (const float*)d_in[7];
    const int*   ir  = (const int*)d_in[8];
    const int*   ic  = (const int*)d_in[9];
    const float* iv  = (const float*)d_in[10];
    const int*   sr  = (const int*)d_in[11];
    const int*   sc  = (const int*)d_in[12];
    const float* sv  = (const float*)d_in[13];
    float* out = (float*)d_out;

    float *socB, *intB, *fuB;
    __half *combB, *socH;
    cudaGetSymbolAddress((void**)&socB,  g_soc);
    cudaGetSymbolAddress((void**)&intB,  g_inter);
    cudaGetSymbolAddress((void**)&fuB,   g_fusedU);
    cudaGetSymbolAddress((void**)&combB, g_comb);
    cudaGetSymbolAddress((void**)&socH,  g_soch);

    int *icnt, *icur, *iptr, *ibs, *scnt, *scur, *sptr, *sbs;
    int2 *icv, *scv;
    cudaGetSymbolAddress((void**)&icnt, g_icnt);
    cudaGetSymbolAddress((void**)&icur, g_icur);
    cudaGetSymbolAddress((void**)&iptr, g_iptr);
    cudaGetSymbolAddress((void**)&icv,  g_icv);
    cudaGetSymbolAddress((void**)&ibs,  g_ibsum);
    cudaGetSymbolAddress((void**)&scnt, g_scnt);
    cudaGetSymbolAddress((void**)&scur, g_scur);
    cudaGetSymbolAddress((void**)&sptr, g_sptr);
    cudaGetSymbolAddress((void**)&scv,  g_scv);
    cudaGetSymbolAddress((void**)&sbs,  g_sbsum);

    const size_t USZ = (size_t)N_USER * LATDIM;
    const size_t NSZ = (size_t)N_NODE * LATDIM;
    const int NB_I = (N_NODE + 2047) / 2048;   // 147
    const int NB_S = (N_USER + 2047) / 2048;   // 49
    const int nI2 = N_ITEM * LATDIM / 2;       // 6.4M half2

    // --- fork a second stream for the soc chain (standard capture fork/join) ---
    cudaStream_t s2;
    cudaStreamCreateWithFlags(&s2, cudaStreamNonBlocking);
    cudaEvent_t evFork, evSoc[4];
    cudaEventCreateWithFlags(&evFork, cudaEventDisableTiming);
    for (int k = 0; k < 4; k++)
        cudaEventCreateWithFlags(&evSoc[k], cudaEventDisableTiming);

    cudaEventRecord(evFork, 0);
    cudaStreamWaitEvent(s2, evFork, 0);

    // === s2: soc CSR build + soc chain (layers 1..4) ===
    hist_rows<<<(E_SOC + 255) / 256, 256, 0, s2>>>(sr, E_SOC, scnt);
    block_sum<<<NB_S, 256, 0, s2>>>(scnt, N_USER, sbs);
    scan_final<<<NB_S, 256, 0, s2>>>(scnt, N_USER, sbs, NB_S, sptr, scur, E_SOC);
    scatter_edges<<<(E_SOC + 255) / 256, 256, 0, s2>>>(sr, sc, sv, E_SOC, scur, scv);

    spmm_f32src<<<(N_USER * 16 + 255) / 256, 256, 0, s2>>>(sptr, scv, uE,
                                                           socB, socH, 0, N_USER);
    cudaEventRecord(evSoc[0], s2);
    for (int k = 1; k < 4; k++) {
        spmm_f16<<<(N_USER * 16 + 255) / 256, 256, 0, s2>>>(
            sptr, scv, socH + (size_t)(k - 1) * USZ,
            socB + (size_t)k * USZ,
            (k < 3) ? socH + (size_t)k * USZ : nullptr, 0, N_USER);
        cudaEventRecord(evSoc[k], s2);
    }

    // === main stream: inter CSR build (+ iE -> comb[0] item region fp16) ===
    hist_rows<<<(E_INTER + 255) / 256, 256>>>(ir, E_INTER, icnt);
    block_sum<<<NB_I, 256>>>(icnt, N_NODE, ibs);
    scan_final<<<NB_I, 256>>>(icnt, N_NODE, ibs, NB_I, iptr, icur, E_INTER);
    {
        int tot = (E_INTER > nI2) ? E_INTER : nI2;
        scatter_conv<<<(tot + 255) / 256, 256>>>(ir, ic, iv, E_INTER, icur, icv,
                                                 (const float2*)iE,
                                                 (__half2*)(combB + USZ), nI2);
    }

    // === main stream: fused layers 0..4 (joins soc layers as needed) ===
    for (int k = 0; k < 5; k++) {
        if (k >= 1) cudaStreamWaitEvent(0, evSoc[k - 1], 0);

        const float* uu  = (k == 0) ? uE : socB + (size_t)(k - 1) * USZ;
        const float* hiU = (k == 0) ? uE : intB + (size_t)(k - 1) * NSZ;
        float* fU = fuB + (size_t)k * USZ;
        __half* combk = combB + (size_t)k * NSZ;

        gate_fuse<<<(N_USER * 32 + 255) / 256, 256>>>(
            uu, hiU, Wg + k * 256, bg + k * 2, fU,
            (k < 4) ? combk : nullptr);

        if (k < 4) {
            spmm_f16<<<(N_NODE * 16 + 255) / 256, 256>>>(
                iptr, icv, combk,
                intB + (size_t)k * NSZ,
                (k < 3) ? combB + (size_t)(k + 1) * NSZ : nullptr,
                N_USER, N_NODE);
        }
    }

    // --- attention readouts ---
    attn5<<<(N_USER * 32 + 255) / 256, 256>>>(
        fuB, fuB + USZ, fuB + 2 * USZ, fuB + 3 * USZ, fuB + 4 * USZ,
        WL1, bL1, out, N_USER);
    attn5<<<(N_ITEM * 32 + 255) / 256, 256>>>(
        iE,
        intB + 0 * NSZ + USZ, intB + 1 * NSZ + USZ,
        intB + 2 * NSZ + USZ, intB + 3 * NSZ + USZ,
        WL2, bL2, out + USZ, N_ITEM);

    // --- cleanup (all s2 work joined into main via evSoc[3] at k=4) ---
    cudaEventDestroy(evFork);
    for (int k = 0; k < 4; k++) cudaEventDestroy(evSoc[k]);
    cudaStreamDestroy(s2);
}

// round 10
// speedup vs baseline: 1.1297x; 1.0221x over previous
#include <cuda_runtime.h>
#include <cuda_fp16.h>

#define N_USER 100000
#define N_ITEM 200000
#define N_NODE 300000
#define LATDIM 64
#define E_INTER 4000000
#define E_SOC   2000000

// fp32 dense scratch (inter keeps USER rows only now)
__device__ __align__(256) float g_soc   [4][(size_t)N_USER * LATDIM];
__device__ __align__(256) float g_interU[4][(size_t)N_USER * LATDIM];
__device__ __align__(256) float g_fusedU[5][(size_t)N_USER * LATDIM];

// fp16 gather sources / shadows
// comb[k] = [ fp16(gate_k user rows) ; fp16(inter_{k} item rows) ]
__device__ __align__(256) __half g_comb[4][(size_t)N_NODE * LATDIM];
__device__ __align__(256) __half g_soch[3][(size_t)N_USER * LATDIM];
__device__ __align__(256) __half g_it3 [(size_t)N_ITEM * LATDIM];   // fp16 item rows of inter spmm 3

// CSR scratch. cnt arrays are self-resetting (zeroed by scan_final after use).
__device__ int  g_icnt[N_NODE];
__device__ int  g_icur[N_NODE];
__device__ int  g_iptr[N_NODE + 1];
__device__ __align__(16) int2 g_icv[E_INTER];
__device__ int  g_ibsum[256];

__device__ int  g_scnt[N_USER];
__device__ int  g_scur[N_USER];
__device__ int  g_sptr[N_USER + 1];
__device__ __align__(16) int2 g_scv[E_SOC];
__device__ int  g_sbsum[256];

// ---------------------------------------------------------------------------
// CSR build
// ---------------------------------------------------------------------------
__global__ void hist_rows(const int* __restrict__ rows, int E, int* __restrict__ cnt)
{
    int i = blockIdx.x * blockDim.x + threadIdx.x;
    if (i < E) atomicAdd(&cnt[rows[i]], 1);
}

__global__ void block_sum(const int* __restrict__ cnt, int N, int* __restrict__ bsum)
{
    __shared__ int sh[256];
    int base = blockIdx.x * 2048;
    int s = 0;
    for (int i = threadIdx.x; i < 2048; i += 256) {
        int idx = base + i;
        s += (idx < N) ? cnt[idx] : 0;
    }
    sh[threadIdx.x] = s;
    __syncthreads();
    for (int o = 128; o; o >>= 1) {
        if (threadIdx.x < o) sh[threadIdx.x] += sh[threadIdx.x + o];
        __syncthreads();
    }
    if (threadIdx.x == 0) bsum[blockIdx.x] = sh[0];
}

__global__ void scan_final(int* __restrict__ cnt, int N,
                           const int* __restrict__ bsum, int NB,
                           int* __restrict__ ptr, int* __restrict__ cur, int E)
{
    __shared__ int shb[256];
    __shared__ int sh[256];
    int t = threadIdx.x;

    shb[t] = (t < NB) ? bsum[t] : 0;
    __syncthreads();
    for (int o = 1; o < 256; o <<= 1) {
        int y = (t >= o) ? shb[t - o] : 0;
        __syncthreads();
        shb[t] += y;
        __syncthreads();
    }
    int block_off = (blockIdx.x == 0) ? 0 : shb[blockIdx.x - 1];

    int base = blockIdx.x * 2048 + t * 8;
    int loc[8];
    int s = 0;
    #pragma unroll
    for (int j = 0; j < 8; j++) {
        int idx = base + j;
        loc[j] = (idx < N) ? cnt[idx] : 0;
        if (idx < N) cnt[idx] = 0;           // self-reset for next call
        s += loc[j];
    }
    sh[t] = s;
    __syncthreads();
    for (int o = 1; o < 256; o <<= 1) {
        int y = (t >= o) ? sh[t - o] : 0;
        __syncthreads();
        sh[t] += y;
        __syncthreads();
    }
    int run = block_off + sh[t] - s;
    #pragma unroll
    for (int j = 0; j < 8; j++) {
        int idx = base + j;
        if (idx < N) { ptr[idx] = run; cur[idx] = run; run += loc[j]; }
    }
    if (blockIdx.x == 0 && t == 0) ptr[N] = E;
}

__global__ void scatter_edges(const int* __restrict__ rows, const int* __restrict__ cols,
                              const float* __restrict__ vals, int E,
                              int* __restrict__ cur, int2* __restrict__ cv)
{
    int i = blockIdx.x * blockDim.x + threadIdx.x;
    if (i >= E) return;
    int p = atomicAdd(&cur[rows[i]], 1);
    cv[p] = make_int2(cols[i], __float_as_int(vals[i]));
}

__global__ void scatter_conv(const int* __restrict__ rows, const int* __restrict__ cols,
                             const float* __restrict__ vals, int E,
                             int* __restrict__ cur, int2* __restrict__ cv,
                             const float2* __restrict__ iE2, __half2* __restrict__ dst2,
                             int nI2)
{
    int i = blockIdx.x * blockDim.x + threadIdx.x;
    if (i < E) {
        int p = atomicAdd(&cur[rows[i]], 1);
        cv[p] = make_int2(cols[i], __float_as_int(vals[i]));
    }
    if (i < nI2) dst2[i] = __float22half2_rn(iE2[i]);
}

// ---------------------------------------------------------------------------
// CSR SpMM v4: 16 lanes per row, pair-lane split.
//   pair = lane>>3 selects which of 2 concurrent edges; q = lane&7 indexes a
//   uint4 (8 halves) of the 128B fp16 source row. One gather LDG.128 serves
//   2 rows x 2 edges. Combine pairs via shfl_xor(8).
//   fp32 store (rows < fmax) by pair 0; fp16 store (rows >= hmin) by pair 1
//   into dsth at row offset (hw - hoff).
// ---------------------------------------------------------------------------
__device__ __forceinline__ void acc8(float* acc, uint4 w, float v)
{
    float2 f0 = __half22float2(*reinterpret_cast<__half2*>(&w.x));
    float2 f1 = __half22float2(*reinterpret_cast<__half2*>(&w.y));
    float2 f2 = __half22float2(*reinterpret_cast<__half2*>(&w.z));
    float2 f3 = __half22float2(*reinterpret_cast<__half2*>(&w.w));
    acc[0] += v * f0.x; acc[1] += v * f0.y;
    acc[2] += v * f1.x; acc[3] += v * f1.y;
    acc[4] += v * f2.x; acc[5] += v * f2.y;
    acc[6] += v * f3.x; acc[7] += v * f3.y;
}

__global__ void __launch_bounds__(256) spmm_f16(
    const int* __restrict__ ptr, const int2* __restrict__ cv,
    const __half* __restrict__ src,
    float* __restrict__ dst, int fmax,
    __half* __restrict__ dsth, int hmin, int hoff, int nrows)
{
    int t = blockIdx.x * blockDim.x + threadIdx.x;
    int hw = t >> 4;
    int lane = threadIdx.x & 15;
    int pair = lane >> 3;
    int q    = lane & 7;
    bool valid = hw < nrows;

    int s = 0, e = 0;
    if (valid) { s = __ldg(ptr + hw); e = __ldg(ptr + hw + 1); }

    float acc[8] = {0.f, 0.f, 0.f, 0.f, 0.f, 0.f, 0.f, 0.f};
    int i = s;
    for (; i + 8 <= e; i += 8) {
        int2 a0 = __ldg(cv + i     + pair);
        int2 a1 = __ldg(cv + i + 2 + pair);
        int2 a2 = __ldg(cv + i + 4 + pair);
        int2 a3 = __ldg(cv + i + 6 + pair);
        uint4 w0 = __ldg((const uint4*)(src + (size_t)a0.x * LATDIM) + q);
        uint4 w1 = __ldg((const uint4*)(src + (size_t)a1.x * LATDIM) + q);
        uint4 w2 = __ldg((const uint4*)(src + (size_t)a2.x * LATDIM) + q);
        uint4 w3 = __ldg((const uint4*)(src + (size_t)a3.x * LATDIM) + q);
        acc8(acc, w0, __int_as_float(a0.y));
        acc8(acc, w1, __int_as_float(a1.y));
        acc8(acc, w2, __int_as_float(a2.y));
        acc8(acc, w3, __int_as_float(a3.y));
    }
    for (; i + 2 <= e; i += 2) {
        int2 a = __ldg(cv + i + pair);
        uint4 w = __ldg((const uint4*)(src + (size_t)a.x * LATDIM) + q);
        acc8(acc, w, __int_as_float(a.y));
    }
    if (i < e && pair == 0) {
        int2 a = __ldg(cv + i);
        uint4 w = __ldg((const uint4*)(src + (size_t)a.x * LATDIM) + q);
        acc8(acc, w, __int_as_float(a.y));
    }

    #pragma unroll
    for (int j = 0; j < 8; j++)
        acc[j] += __shfl_xor_sync(0xffffffffu, acc[j], 8);

    if (valid && pair == 0 && hw < fmax) {
        float4 lo = make_float4(acc[0], acc[1], acc[2], acc[3]);
        float4 hi = make_float4(acc[4], acc[5], acc[6], acc[7]);
        float4* d = (float4*)(dst + (size_t)hw * LATDIM);
        d[2 * q]     = lo;
        d[2 * q + 1] = hi;
    }
    if (valid && pair == 1 && dsth != nullptr && hw >= hmin) {
        __half2 h0 = __floats2half2_rn(acc[0], acc[1]);
        __half2 h1 = __floats2half2_rn(acc[2], acc[3]);
        __half2 h2 = __floats2half2_rn(acc[4], acc[5]);
        __half2 h3 = __floats2half2_rn(acc[6], acc[7]);
        uint4 pk;
        pk.x = *reinterpret_cast<unsigned*>(&h0);
        pk.y = *reinterpret_cast<unsigned*>(&h1);
        pk.z = *reinterpret_cast<unsigned*>(&h2);
        pk.w = *reinterpret_cast<unsigned*>(&h3);
        ((uint4*)(dsth + (size_t)(hw - hoff) * LATDIM))[q] = pk;
    }
}

// fp32-source variant (R7 form; only soc layer 0, off the critical path)
__global__ void __launch_bounds__(256) spmm_f32src(
    const int* __restrict__ ptr, const int2* __restrict__ cv,
    const float* __restrict__ src,
    float* __restrict__ dst, __half* __restrict__ dsth, int nrows)
{
    int hw = (blockIdx.x * blockDim.x + threadIdx.x) >> 4;
    int q  = threadIdx.x & 15;
    if (hw >= nrows) return;
    int s = __ldg(ptr + hw);
    int e = __ldg(ptr + hw + 1);
    float4 acc = make_float4(0.f, 0.f, 0.f, 0.f);
    int i = s;
    for (; i + 4 <= e; i += 4) {
        int2 a0 = __ldg(cv + i),     a1 = __ldg(cv + i + 1);
        int2 a2 = __ldg(cv + i + 2), a3 = __ldg(cv + i + 3);
        float4 x0 = __ldg((const float4*)(src + (size_t)a0.x * LATDIM) + q);
        float4 x1 = __ldg((const float4*)(src + (size_t)a1.x * LATDIM) + q);
        float4 x2 = __ldg((const float4*)(src + (size_t)a2.x * LATDIM) + q);
        float4 x3 = __ldg((const float4*)(src + (size_t)a3.x * LATDIM) + q);
        float v0 = __int_as_float(a0.y), v1 = __int_as_float(a1.y);
        float v2 = __int_as_float(a2.y), v3 = __int_as_float(a3.y);
        acc.x += v0 * x0.x; acc.y += v0 * x0.y; acc.z += v0 * x0.z; acc.w += v0 * x0.w;
        acc.x += v1 * x1.x; acc.y += v1 * x1.y; acc.z += v1 * x1.z; acc.w += v1 * x1.w;
        acc.x += v2 * x2.x; acc.y += v2 * x2.y; acc.z += v2 * x2.z; acc.w += v2 * x2.w;
        acc.x += v3 * x3.x; acc.y += v3 * x3.y; acc.z += v3 * x3.z; acc.w += v3 * x3.w;
    }
    for (; i < e; i++) {
        int2 a = __ldg(cv + i);
        float4 x = __ldg((const float4*)(src + (size_t)a.x * LATDIM) + q);
        float v = __int_as_float(a.y);
        acc.x += v * x.x; acc.y += v * x.y; acc.z += v * x.z; acc.w += v * x.w;
    }
    ((float4*)(dst + (size_t)hw * LATDIM))[q] = acc;
    __half2 h0 = __floats2half2_rn(acc.x, acc.y);
    __half2 h1 = __floats2half2_rn(acc.z, acc.w);
    uint2 pk;
    pk.x = *reinterpret_cast<unsigned*>(&h0);
    pk.y = *reinterpret_cast<unsigned*>(&h1);
    ((uint2*)(dsth + (size_t)hw * LATDIM))[q] = pk;
}

// ---------------------------------------------------------------------------
// Gate + fuse (fp32 in, fp32 out + optional fp16 out into comb user region)
// ---------------------------------------------------------------------------
__global__ void gate_fuse(const float* __restrict__ uu, const float* __restrict__ hi,
                          const float* __restrict__ Wg, const float* __restrict__ bg,
                          float* __restrict__ out, __half* __restrict__ outh)
{
    int gt = blockIdx.x * blockDim.x + threadIdx.x;
    int u = gt >> 5;
    int lane = threadIdx.x & 31;
    if (u >= N_USER) return;

    float2 za = ((const float2*)(uu + (size_t)u * LATDIM))[lane];
    float2 ha = ((const float2*)(hi + (size_t)u * LATDIM))[lane];

    int d = 2 * lane;
    float p0 = za.x * Wg[d]       + za.y * Wg[d + 1]
             + ha.x * Wg[64 + d]  + ha.y * Wg[64 + d + 1];
    float p1 = za.x * Wg[128 + d]      + za.y * Wg[128 + d + 1]
             + ha.x * Wg[128 + 64 + d] + ha.y * Wg[128 + 64 + d + 1];
    #pragma unroll
    for (int o = 16; o; o >>= 1) {
        p0 += __shfl_xor_sync(0xffffffffu, p0, o);
        p1 += __shfl_xor_sync(0xffffffffu, p1, o);
    }
    float l0 = p0 + bg[0];
    float l1 = p1 + bg[1];
    l0 = l0 > 0.f ? l0 : 0.01f * l0;
    l1 = l1 > 0.f ? l1 : 0.01f * l1;
    float mx = fmaxf(l0, l1);
    float e0 = __expf(l0 - mx), e1 = __expf(l1 - mx);
    float inv = 1.f / (e0 + e1);
    float m0 = e0 * inv, m1 = e1 * inv;

    float2 o2 = make_float2(za.x * m0 + ha.x * m1, za.y * m0 + ha.y * m1);
    ((float2*)(out + (size_t)u * LATDIM))[lane] = o2;
    if (outh != nullptr)
        ((__half2*)(outh + (size_t)u * LATDIM))[lane] = __float22half2_rn(o2);
}

// ---------------------------------------------------------------------------
// 5-way attention readout — fp32 sources (user side)
// ---------------------------------------------------------------------------
__global__ void attn5(const float* __restrict__ f0, const float* __restrict__ f1,
                      const float* __restrict__ f2, const float* __restrict__ f3,
                      const float* __restrict__ f4,
                      const float* __restrict__ W, const float* __restrict__ b,
                      float* __restrict__ out, int N)
{
    __shared__ float sW[5 * 320];
    __shared__ float sb[5];
    for (int i = threadIdx.x; i < 5 * 320; i += blockDim.x) sW[i] = W[i];
    if (threadIdx.x < 5) sb[threadIdx.x] = b[threadIdx.x];
    __syncthreads();

    int gt = blockIdx.x * blockDim.x + threadIdx.x;
    int u = gt >> 5;
    int lane = threadIdx.x & 31;
    if (u >= N) return;

    const float* fp[5] = {f0, f1, f2, f3, f4};
    float2 f[5];
    #pragma unroll
    for (int k = 0; k < 5; k++)
        f[k] = ((const float2*)(fp[k] + (size_t)u * LATDIM))[lane];

    int d = 2 * lane;
    float p[5];
    #pragma unroll
    for (int j = 0; j < 5; j++) {
        float acc = 0.f;
        #pragma unroll
        for (int k = 0; k < 5; k++) {
            acc += f[k].x * sW[j * 320 + k * 64 + d];
            acc += f[k].y * sW[j * 320 + k * 64 + d + 1];
        }
        p[j] = acc;
    }
    #pragma unroll
    for (int j = 0; j < 5; j++)
        #pragma unroll
        for (int o = 16; o; o >>= 1)
            p[j] += __shfl_xor_sync(0xffffffffu, p[j], o);

    float mx = -1e30f;
    #pragma unroll
    for (int j = 0; j < 5; j++) {
        float l = p[j] + sb[j];
        l = l > 0.f ? l : 0.01f * l;
        p[j] = l;
        mx = fmaxf(mx, l);
    }
    float se = 0.f;
    #pragma unroll
    for (int j = 0; j < 5; j++) { p[j] = __expf(p[j] - mx); se += p[j]; }
    float inv = 1.f / se;

    float2 o2 = make_float2(0.f, 0.f);
    #pragma unroll
    for (int k = 0; k < 5; k++) {
        float w = p[k] * inv;
        o2.x += w * f[k].x;
        o2.y += w * f[k].y;
    }
    ((float2*)(out + (size_t)u * LATDIM))[lane] = o2;
}

// ---------------------------------------------------------------------------
// 5-way attention readout — item side: f0 fp32 (iE), f1..f4 fp16 shadows
// ---------------------------------------------------------------------------
__global__ void attn5h(const float* __restrict__ f0,
                       const __half* __restrict__ h1, const __half* __restrict__ h2,
                       const __half* __restrict__ h3, const __half* __restrict__ h4,
                       const float* __restrict__ W, const float* __restrict__ b,
                       float* __restrict__ out, int N)
{
    __shared__ float sW[5 * 320];
    __shared__ float sb[5];
    for (int i = threadIdx.x; i < 5 * 320; i += blockDim.x) sW[i] = W[i];
    if (threadIdx.x < 5) sb[threadIdx.x] = b[threadIdx.x];
    __syncthreads();

    int gt = blockIdx.x * blockDim.x + threadIdx.x;
    int u = gt >> 5;
    int lane = threadIdx.x & 31;
    if (u >= N) return;

    float2 f[5];
    f[0] = ((const float2*)(f0 + (size_t)u * LATDIM))[lane];
    const __half* hp[4] = {h1, h2, h3, h4};
    #pragma unroll
    for (int k = 0; k < 4; k++)
        f[k + 1] = __half22float2(((const __half2*)(hp[k] + (size_t)u * LATDIM))[lane]);

    int d = 2 * lane;
    float p[5];
    #pragma unroll
    for (int j = 0; j < 5; j++) {
        float acc = 0.f;
        #pragma unroll
        for (int k = 0; k < 5; k++) {
            acc += f[k].x * sW[j * 320 + k * 64 + d];
            acc += f[k].y * sW[j * 320 + k * 64 + d + 1];
        }
        p[j] = acc;
    }
    #pragma unroll
    for (int j = 0; j < 5; j++)
        #pragma unroll
        for (int o = 16; o; o >>= 1)
            p[j] += __shfl_xor_sync(0xffffffffu, p[j], o);

    float mx = -1e30f;
    #pragma unroll
    for (int j = 0; j < 5; j++) {
        float l = p[j] + sb[j];
        l = l > 0.f ? l : 0.01f * l;
        p[j] = l;
        mx = fmaxf(mx, l);
    }
    float se = 0.f;
    #pragma unroll
    for (int j = 0; j < 5; j++) { p[j] = __expf(p[j] - mx); se += p[j]; }
    float inv = 1.f / se;

    float2 o2 = make_float2(0.f, 0.f);
    #pragma unroll
    for (int k = 0; k < 5; k++) {
        float w = p[k] * inv;
        o2.x += w * f[k].x;
        o2.y += w * f[k].y;
    }
    ((float2*)(out + (size_t)u * LATDIM))[lane] = o2;
}

// ---------------------------------------------------------------------------

extern "C" void kernel_launch(void* const* d_in, const int* in_sizes, int n_in,
                              void* d_out, int out_size)
{
    const float* uE  = (const float*)d_in[0];
    const float* iE  = (const float*)d_in[1];
    const float* Wg  = (const float*)d_in[2];
    const float* bg  = (const float*)d_in[3];
    const float* WL1 = (const float*)d_in[4];
    const float* bL1 = (const float*)d_in[5];
    const float* WL2 = (const float*)d_in[6];
    const float* bL2 = (const float*)d_in[7];
    const int*   ir  = (const int*)d_in[8];
    const int*   ic  = (const int*)d_in[9];
    const float* iv  = (const float*)d_in[10];
    const int*   sr  = (const int*)d_in[11];
    const int*   sc  = (const int*)d_in[12];
    const float* sv  = (const float*)d_in[13];
    float* out = (float*)d_out;

    float *socB, *intU, *fuB;
    __half *combB, *socH, *it3;
    cudaGetSymbolAddress((void**)&socB,  g_soc);
    cudaGetSymbolAddress((void**)&intU,  g_interU);
    cudaGetSymbolAddress((void**)&fuB,   g_fusedU);
    cudaGetSymbolAddress((void**)&combB, g_comb);
    cudaGetSymbolAddress((void**)&socH,  g_soch);
    cudaGetSymbolAddress((void**)&it3,   g_it3);

    int *icnt, *icur, *iptr, *ibs, *scnt, *scur, *sptr, *sbs;
    int2 *icv, *scv;
    cudaGetSymbolAddress((void**)&icnt, g_icnt);
    cudaGetSymbolAddress((void**)&icur, g_icur);
    cudaGetSymbolAddress((void**)&iptr, g_iptr);
    cudaGetSymbolAddress((void**)&icv,  g_icv);
    cudaGetSymbolAddress((void**)&ibs,  g_ibsum);
    cudaGetSymbolAddress((void**)&scnt, g_scnt);
    cudaGetSymbolAddress((void**)&scur, g_scur);
    cudaGetSymbolAddress((void**)&sptr, g_sptr);
    cudaGetSymbolAddress((void**)&scv,  g_scv);
    cudaGetSymbolAddress((void**)&sbs,  g_sbsum);

    const size_t USZ = (size_t)N_USER * LATDIM;
    const size_t NSZ = (size_t)N_NODE * LATDIM;
    const int NB_I = (N_NODE + 2047) / 2048;   // 147
    const int NB_S = (N_USER + 2047) / 2048;   // 49
    const int nI2 = N_ITEM * LATDIM / 2;       // 6.4M half2

    // --- fork a second stream for the soc chain ---
    cudaStream_t s2;
    cudaStreamCreateWithFlags(&s2, cudaStreamNonBlocking);
    cudaEvent_t evFork, evSoc[4];
    cudaEventCreateWithFlags(&evFork, cudaEventDisableTiming);
    for (int k = 0; k < 4; k++)
        cudaEventCreateWithFlags(&evSoc[k], cudaEventDisableTiming);

    cudaEventRecord(evFork, 0);
    cudaStreamWaitEvent(s2, evFork, 0);

    // === s2: soc CSR build + soc chain (layers 1..4) ===
    hist_rows<<<(E_SOC + 255) / 256, 256, 0, s2>>>(sr, E_SOC, scnt);
    block_sum<<<NB_S, 256, 0, s2>>>(scnt, N_USER, sbs);
    scan_final<<<NB_S, 256, 0, s2>>>(scnt, N_USER, sbs, NB_S, sptr, scur, E_SOC);
    scatter_edges<<<(E_SOC + 255) / 256, 256, 0, s2>>>(sr, sc, sv, E_SOC, scur, scv);

    spmm_f32src<<<(N_USER * 16 + 255) / 256, 256, 0, s2>>>(sptr, scv, uE,
                                                           socB, socH, N_USER);
    cudaEventRecord(evSoc[0], s2);
    for (int k = 1; k < 4; k++) {
        spmm_f16<<<(N_USER * 16 + 255) / 256, 256, 0, s2>>>(
            sptr, scv, socH + (size_t)(k - 1) * USZ,
            socB + (size_t)k * USZ, N_USER,
            (k < 3) ? socH + (size_t)k * USZ : nullptr, 0, 0, N_USER);
        cudaEventRecord(evSoc[k], s2);
    }

    // === main stream: inter CSR build (+ iE -> comb[0] item region fp16) ===
    hist_rows<<<(E_INTER + 255) / 256, 256>>>(ir, E_INTER, icnt);
    block_sum<<<NB_I, 256>>>(icnt, N_NODE, ibs);
    scan_final<<<NB_I, 256>>>(icnt, N_NODE, ibs, NB_I, iptr, icur, E_INTER);
    {
        int tot = (E_INTER > nI2) ? E_INTER : nI2;
        scatter_conv<<<(tot + 255) / 256, 256>>>(ir, ic, iv, E_INTER, icur, icv,
                                                 (const float2*)iE,
                                                 (__half2*)(combB + USZ), nI2);
    }

    // === main stream: fused layers 0..4 ===
    for (int k = 0; k < 5; k++) {
        if (k >= 1) cudaStreamWaitEvent(0, evSoc[k - 1], 0);

        const float* uu  = (k == 0) ? uE : socB + (size_t)(k - 1) * USZ;
        const float* hiU = (k == 0) ? uE : intU + (size_t)(k - 1) * USZ;
        float* fU = fuB + (size_t)k * USZ;
        __half* combk = combB + (size_t)k * NSZ;

        gate_fuse<<<(N_USER * 32 + 255) / 256, 256>>>(
            uu, hiU, Wg + k * 256, bg + k * 2, fU,
            (k < 4) ? combk : nullptr);

        if (k < 4) {
            // fp32 user rows -> intU[k]; fp16 item rows -> comb[k+1] (k<3) or it3
            __half* dsth = (k < 3) ? combB + (size_t)(k + 1) * NSZ + USZ : it3;
            spmm_f16<<<(N_NODE * 16 + 255) / 256, 256>>>(
                iptr, icv, combk,
                intU + (size_t)k * USZ, N_USER,
                dsth, N_USER, N_USER, N_NODE);
        }
    }

    // --- attention readouts ---
    attn5<<<(N_USER * 32 + 255) / 256, 256>>>(
        fuB, fuB + USZ, fuB + 2 * USZ, fuB + 3 * USZ, fuB + 4 * USZ,
        WL1, bL1, out, N_USER);
    attn5h<<<(N_ITEM * 32 + 255) / 256, 256>>>(
        iE,
        combB + 1 * NSZ + USZ, combB + 2 * NSZ + USZ, combB + 3 * NSZ + USZ, it3,
        WL2, bL2, out + USZ, N_ITEM);

    // --- cleanup ---
    cudaEventDestroy(evFork);
    for (int k = 0; k < 4; k++) cudaEventDestroy(evSoc[k]);
    cudaStreamDestroy(s2);
}

// round 12
// speedup vs baseline: 1.1474x; 1.0157x over previous
#include <cuda_runtime.h>
#include <cuda_fp16.h>

#define N_USER 100000
#define N_ITEM 200000
#define N_NODE 300000
#define LATDIM 64
#define E_INTER 4000000
#define E_SOC   2000000

// fp32 dense scratch (inter keeps USER rows only)
__device__ __align__(256) float g_soc   [4][(size_t)N_USER * LATDIM];
__device__ __align__(256) float g_interU[4][(size_t)N_USER * LATDIM];
__device__ __align__(256) float g_fusedU[5][(size_t)N_USER * LATDIM];

// fp16 gather sources / shadows
// comb[k] = [ fp16(gate_k user rows) ; fp16(inter_{k} item rows) ]
__device__ __align__(256) __half g_comb[4][(size_t)N_NODE * LATDIM];
__device__ __align__(256) __half g_soch[3][(size_t)N_USER * LATDIM];
__device__ __align__(256) __half g_it3 [(size_t)N_ITEM * LATDIM];   // item rows of inter spmm 3

// CSR scratch. cnt arrays self-reset (zeroed by scan_final after use).
__device__ int  g_icnt[N_NODE];
__device__ int  g_icur[N_NODE];
__device__ int  g_iptr[N_NODE + 1];
__device__ __align__(16) int2 g_icv[E_INTER];
__device__ int  g_ibsum[256];

__device__ int  g_scnt[N_USER];
__device__ int  g_scur[N_USER];
__device__ int  g_sptr[N_USER + 1];
__device__ __align__(16) int2 g_scv[E_SOC];
__device__ int  g_sbsum[256];

// ---------------------------------------------------------------------------
// CSR build
// ---------------------------------------------------------------------------
__global__ void hist_rows(const int* __restrict__ rows, int E, int* __restrict__ cnt)
{
    int i = blockIdx.x * blockDim.x + threadIdx.x;
    if (i < E) atomicAdd(&cnt[rows[i]], 1);
}

__global__ void block_sum(const int* __restrict__ cnt, int N, int* __restrict__ bsum)
{
    __shared__ int sh[256];
    int base = blockIdx.x * 2048;
    int s = 0;
    for (int i = threadIdx.x; i < 2048; i += 256) {
        int idx = base + i;
        s += (idx < N) ? cnt[idx] : 0;
    }
    sh[threadIdx.x] = s;
    __syncthreads();
    for (int o = 128; o; o >>= 1) {
        if (threadIdx.x < o) sh[threadIdx.x] += sh[threadIdx.x + o];
        __syncthreads();
    }
    if (threadIdx.x == 0) bsum[blockIdx.x] = sh[0];
}

__global__ void scan_final(int* __restrict__ cnt, int N,
                           const int* __restrict__ bsum, int NB,
                           int* __restrict__ ptr, int* __restrict__ cur, int E)
{
    __shared__ int shb[256];
    __shared__ int sh[256];
    int t = threadIdx.x;

    shb[t] = (t < NB) ? bsum[t] : 0;
    __syncthreads();
    for (int o = 1; o < 256; o <<= 1) {
        int y = (t >= o) ? shb[t - o] : 0;
        __syncthreads();
        shb[t] += y;
        __syncthreads();
    }
    int block_off = (blockIdx.x == 0) ? 0 : shb[blockIdx.x - 1];

    int base = blockIdx.x * 2048 + t * 8;
    int loc[8];
    int s = 0;
    #pragma unroll
    for (int j = 0; j < 8; j++) {
        int idx = base + j;
        loc[j] = (idx < N) ? cnt[idx] : 0;
        if (idx < N) cnt[idx] = 0;           // self-reset for next call
        s += loc[j];
    }
    sh[t] = s;
    __syncthreads();
    for (int o = 1; o < 256; o <<= 1) {
        int y = (t >= o) ? sh[t - o] : 0;
        __syncthreads();
        sh[t] += y;
        __syncthreads();
    }
    int run = block_off + sh[t] - s;
    #pragma unroll
    for (int j = 0; j < 8; j++) {
        int idx = base + j;
        if (idx < N) { ptr[idx] = run; cur[idx] = run; run += loc[j]; }
    }
    if (blockIdx.x == 0 && t == 0) ptr[N] = E;
}

__global__ void scatter_edges(const int* __restrict__ rows, const int* __restrict__ cols,
                              const float* __restrict__ vals, int E,
                              int* __restrict__ cur, int2* __restrict__ cv)
{
    int i = blockIdx.x * blockDim.x + threadIdx.x;
    if (i >= E) return;
    int p = atomicAdd(&cur[rows[i]], 1);
    cv[p] = make_int2(cols[i], __float_as_int(vals[i]));
}

__global__ void scatter_conv(const int* __restrict__ rows, const int* __restrict__ cols,
                             const float* __restrict__ vals, int E,
                             int* __restrict__ cur, int2* __restrict__ cv,
                             const float2* __restrict__ iE2, __half2* __restrict__ dst2,
                             int nI2)
{
    int i = blockIdx.x * blockDim.x + threadIdx.x;
    if (i < E) {
        int p = atomicAdd(&cur[rows[i]], 1);
        cv[p] = make_int2(cols[i], __float_as_int(vals[i]));
    }
    if (i < nI2) dst2[i] = __float22half2_rn(iE2[i]);
}

// ---------------------------------------------------------------------------
// CSR SpMM: 16 lanes/row, pair-lane split; row range [r0, r1).
//   pair = lane>>3 processes 2 edges of the same row concurrently; q = lane&7
//   indexes a uint4 (16B) of the 128B fp16 source row. Combine via shfl_xor(8).
//   fp32 store by pair 0 iff dst != null (indexed by row);
//   fp16 store by pair 1 iff dsth != null (indexed by row - hoff).
// ---------------------------------------------------------------------------
__device__ __forceinline__ void acc8(float* acc, uint4 w, float v)
{
    float2 f0 = __half22float2(*reinterpret_cast<__half2*>(&w.x));
    float2 f1 = __half22float2(*reinterpret_cast<__half2*>(&w.y));
    float2 f2 = __half22float2(*reinterpret_cast<__half2*>(&w.z));
    float2 f3 = __half22float2(*reinterpret_cast<__half2*>(&w.w));
    acc[0] += v * f0.x; acc[1] += v * f0.y;
    acc[2] += v * f1.x; acc[3] += v * f1.y;
    acc[4] += v * f2.x; acc[5] += v * f2.y;
    acc[6] += v * f3.x; acc[7] += v * f3.y;
}

__global__ void __launch_bounds__(256) spmm_f16(
    const int* __restrict__ ptr, const int2* __restrict__ cv,
    const __half* __restrict__ src,
    float* __restrict__ dst,
    __half* __restrict__ dsth, int hoff, int r0, int r1)
{
    int t = blockIdx.x * blockDim.x + threadIdx.x;
    int row = r0 + (t >> 4);
    int lane = threadIdx.x & 15;
    int pair = lane >> 3;
    int q    = lane & 7;
    bool valid = row < r1;

    int s = 0, e = 0;
    if (valid) { s = __ldg(ptr + row); e = __ldg(ptr + row + 1); }

    float acc[8] = {0.f, 0.f, 0.f, 0.f, 0.f, 0.f, 0.f, 0.f};
    int i = s;
    for (; i + 8 <= e; i += 8) {
        int2 a0 = __ldg(cv + i     + pair);
        int2 a1 = __ldg(cv + i + 2 + pair);
        int2 a2 = __ldg(cv + i + 4 + pair);
        int2 a3 = __ldg(cv + i + 6 + pair);
        uint4 w0 = __ldg((const uint4*)(src + (size_t)a0.x * LATDIM) + q);
        uint4 w1 = __ldg((const uint4*)(src + (size_t)a1.x * LATDIM) + q);
        uint4 w2 = __ldg((const uint4*)(src + (size_t)a2.x * LATDIM) + q);
        uint4 w3 = __ldg((const uint4*)(src + (size_t)a3.x * LATDIM) + q);
        acc8(acc, w0, __int_as_float(a0.y));
        acc8(acc, w1, __int_as_float(a1.y));
        acc8(acc, w2, __int_as_float(a2.y));
        acc8(acc, w3, __int_as_float(a3.y));
    }
    for (; i + 2 <= e; i += 2) {
        int2 a = __ldg(cv + i + pair);
        uint4 w = __ldg((const uint4*)(src + (size_t)a.x * LATDIM) + q);
        acc8(acc, w, __int_as_float(a.y));
    }
    if (i < e && pair == 0) {
        int2 a = __ldg(cv + i);
        uint4 w = __ldg((const uint4*)(src + (size_t)a.x * LATDIM) + q);
        acc8(acc, w, __int_as_float(a.y));
    }

    #pragma unroll
    for (int j = 0; j < 8; j++)
        acc[j] += __shfl_xor_sync(0xffffffffu, acc[j], 8);

    if (valid && pair == 0 && dst != nullptr) {
        float4 lo = make_float4(acc[0], acc[1], acc[2], acc[3]);
        float4 hi = make_float4(acc[4], acc[5], acc[6], acc[7]);
        float4* d = (float4*)(dst + (size_t)row * LATDIM);
        d[2 * q]     = lo;
        d[2 * q + 1] = hi;
    }
    if (valid && pair == 1 && dsth != nullptr) {
        __half2 h0 = __floats2half2_rn(acc[0], acc[1]);
        __half2 h1 = __floats2half2_rn(acc[2], acc[3]);
        __half2 h2 = __floats2half2_rn(acc[4], acc[5]);
        __half2 h3 = __floats2half2_rn(acc[6], acc[7]);
        uint4 pk;
        pk.x = *reinterpret_cast<unsigned*>(&h0);
        pk.y = *reinterpret_cast<unsigned*>(&h1);
        pk.z = *reinterpret_cast<unsigned*>(&h2);
        pk.w = *reinterpret_cast<unsigned*>(&h3);
        ((uint4*)(dsth + (size_t)(row - hoff) * LATDIM))[q] = pk;
    }
}

// fp32-source variant (soc layer 0 only; off the critical path)
__global__ void __launch_bounds__(256) spmm_f32src(
    const int* __restrict__ ptr, const int2* __restrict__ cv,
    const float* __restrict__ src,
    float* __restrict__ dst, __half* __restrict__ dsth, int nrows)
{
    int hw = (blockIdx.x * blockDim.x + threadIdx.x) >> 4;
    int q  = threadIdx.x & 15;
    if (hw >= nrows) return;
    int s = __ldg(ptr + hw);
    int e = __ldg(ptr + hw + 1);
    float4 acc = make_float4(0.f, 0.f, 0.f, 0.f);
    int i = s;
    for (; i + 4 <= e; i += 4) {
        int2 a0 = __ldg(cv + i),     a1 = __ldg(cv + i + 1);
        int2 a2 = __ldg(cv + i + 2), a3 = __ldg(cv + i + 3);
        float4 x0 = __ldg((const float4*)(src + (size_t)a0.x * LATDIM) + q);
        float4 x1 = __ldg((const float4*)(src + (size_t)a1.x * LATDIM) + q);
        float4 x2 = __ldg((const float4*)(src + (size_t)a2.x * LATDIM) + q);
        float4 x3 = __ldg((const float4*)(src + (size_t)a3.x * LATDIM) + q);
        float v0 = __int_as_float(a0.y), v1 = __int_as_float(a1.y);
        float v2 = __int_as_float(a2.y), v3 = __int_as_float(a3.y);
        acc.x += v0 * x0.x; acc.y += v0 * x0.y; acc.z += v0 * x0.z; acc.w += v0 * x0.w;
        acc.x += v1 * x1.x; acc.y += v1 * x1.y; acc.z += v1 * x1.z; acc.w += v1 * x1.w;
        acc.x += v2 * x2.x; acc.y += v2 * x2.y; acc.z += v2 * x2.z; acc.w += v2 * x2.w;
        acc.x += v3 * x3.x; acc.y += v3 * x3.y; acc.z += v3 * x3.z; acc.w += v3 * x3.w;
    }
    for (; i < e; i++) {
        int2 a = __ldg(cv + i);
        float4 x = __ldg((const float4*)(src + (size_t)a.x * LATDIM) + q);
        float v = __int_as_float(a.y);
        acc.x += v * x.x; acc.y += v * x.y; acc.z += v * x.z; acc.w += v * x.w;
    }
    ((float4*)(dst + (size_t)hw * LATDIM))[q] = acc;
    __half2 h0 = __floats2half2_rn(acc.x, acc.y);
    __half2 h1 = __floats2half2_rn(acc.z, acc.w);
    uint2 pk;
    pk.x = *reinterpret_cast<unsigned*>(&h0);
    pk.y = *reinterpret_cast<unsigned*>(&h1);
    ((uint2*)(dsth + (size_t)hw * LATDIM))[q] = pk;
}

// ---------------------------------------------------------------------------
// Gate + fuse (fp32 in, fp32 out + optional fp16 out into comb user region)
// ---------------------------------------------------------------------------
__global__ void gate_fuse(const float* __restrict__ uu, const float* __restrict__ hi,
                          const float* __restrict__ Wg, const float* __restrict__ bg,
                          float* __restrict__ out, __half* __restrict__ outh)
{
    int gt = blockIdx.x * blockDim.x + threadIdx.x;
    int u = gt >> 5;
    int lane = threadIdx.x & 31;
    if (u >= N_USER) return;

    float2 za = ((const float2*)(uu + (size_t)u * LATDIM))[lane];
    float2 ha = ((const float2*)(hi + (size_t)u * LATDIM))[lane];

    int d = 2 * lane;
    float p0 = za.x * Wg[d]       + za.y * Wg[d + 1]
             + ha.x * Wg[64 + d]  + ha.y * Wg[64 + d + 1];
    float p1 = za.x * Wg[128 + d]      + za.y * Wg[128 + d + 1]
             + ha.x * Wg[128 + 64 + d] + ha.y * Wg[128 + 64 + d + 1];
    #pragma unroll
    for (int o = 16; o; o >>= 1) {
        p0 += __shfl_xor_sync(0xffffffffu, p0, o);
        p1 += __shfl_xor_sync(0xffffffffu, p1, o);
    }
    float l0 = p0 + bg[0];
    float l1 = p1 + bg[1];
    l0 = l0 > 0.f ? l0 : 0.01f * l0;
    l1 = l1 > 0.f ? l1 : 0.01f * l1;
    float mx = fmaxf(l0, l1);
    float e0 = __expf(l0 - mx), e1 = __expf(l1 - mx);
    float inv = 1.f / (e0 + e1);
    float m0 = e0 * inv, m1 = e1 * inv;

    float2 o2 = make_float2(za.x * m0 + ha.x * m1, za.y * m0 + ha.y * m1);
    ((float2*)(out + (size_t)u * LATDIM))[lane] = o2;
    if (outh != nullptr)
        ((__half2*)(outh + (size_t)u * LATDIM))[lane] = __float22half2_rn(o2);
}

// ---------------------------------------------------------------------------
// 5-way attention readout — fp32 sources (user side)
// ---------------------------------------------------------------------------
__global__ void attn5(const float* __restrict__ f0, const float* __restrict__ f1,
                      const float* __restrict__ f2, const float* __restrict__ f3,
                      const float* __restrict__ f4,
                      const float* __restrict__ W, const float* __restrict__ b,
                      float* __restrict__ out, int N)
{
    __shared__ float sW[5 * 320];
    __shared__ float sb[5];
    for (int i = threadIdx.x; i < 5 * 320; i += blockDim.x) sW[i] = W[i];
    if (threadIdx.x < 5) sb[threadIdx.x] = b[threadIdx.x];
    __syncthreads();

    int gt = blockIdx.x * blockDim.x + threadIdx.x;
    int u = gt >> 5;
    int lane = threadIdx.x & 31;
    if (u >= N) return;

    const float* fp[5] = {f0, f1, f2, f3, f4};
    float2 f[5];
    #pragma unroll
    for (int k = 0; k < 5; k++)
        f[k] = ((const float2*)(fp[k] + (size_t)u * LATDIM))[lane];

    int d = 2 * lane;
    float p[5];
    #pragma unroll
    for (int j = 0; j < 5; j++) {
        float acc = 0.f;
        #pragma unroll
        for (int k = 0; k < 5; k++) {
            acc += f[k].x * sW[j * 320 + k * 64 + d];
            acc += f[k].y * sW[j * 320 + k * 64 + d + 1];
        }
        p[j] = acc;
    }
    #pragma unroll
    for (int j = 0; j < 5; j++)
        #pragma unroll
        for (int o = 16; o; o >>= 1)
            p[j] += __shfl_xor_sync(0xffffffffu, p[j], o);

    float mx = -1e30f;
    #pragma unroll
    for (int j = 0; j < 5; j++) {
        float l = p[j] + sb[j];
        l = l > 0.f ? l : 0.01f * l;
        p[j] = l;
        mx = fmaxf(mx, l);
    }
    float se = 0.f;
    #pragma unroll
    for (int j = 0; j < 5; j++) { p[j] = __expf(p[j] - mx); se += p[j]; }
    float inv = 1.f / se;

    float2 o2 = make_float2(0.f, 0.f);
    #pragma unroll
    for (int k = 0; k < 5; k++) {
        float w = p[k] * inv;
        o2.x += w * f[k].x;
        o2.y += w * f[k].y;
    }
    ((float2*)(out + (size_t)u * LATDIM))[lane] = o2;
}

// ---------------------------------------------------------------------------
// 5-way attention readout — item side: f0 fp32 (iE), f1..f4 fp16 shadows
// ---------------------------------------------------------------------------
__global__ void attn5h(const float* __restrict__ f0,
                       const __half* __restrict__ h1, const __half* __restrict__ h2,
                       const __half* __restrict__ h3, const __half* __restrict__ h4,
                       const float* __restrict__ W, const float* __restrict__ b,
                       float* __restrict__ out, int N)
{
    __shared__ float sW[5 * 320];
    __shared__ float sb[5];
    for (int i = threadIdx.x; i < 5 * 320; i += blockDim.x) sW[i] = W[i];
    if (threadIdx.x < 5) sb[threadIdx.x] = b[threadIdx.x];
    __syncthreads();

    int gt = blockIdx.x * blockDim.x + threadIdx.x;
    int u = gt >> 5;
    int lane = threadIdx.x & 31;
    if (u >= N) return;

    float2 f[5];
    f[0] = ((const float2*)(f0 + (size_t)u * LATDIM))[lane];
    const __half* hp[4] = {h1, h2, h3, h4};
    #pragma unroll
    for (int k = 0; k < 4; k++)
        f[k + 1] = __half22float2(((const __half2*)(hp[k] + (size_t)u * LATDIM))[lane]);

    int d = 2 * lane;
    float p[5];
    #pragma unroll
    for (int j = 0; j < 5; j++) {
        float acc = 0.f;
        #pragma unroll
        for (int k = 0; k < 5; k++) {
            acc += f[k].x * sW[j * 320 + k * 64 + d];
            acc += f[k].y * sW[j * 320 + k * 64 + d + 1];
        }
        p[j] = acc;
    }
    #pragma unroll
    for (int j = 0; j < 5; j++)
        #pragma unroll
        for (int o = 16; o; o >>= 1)
            p[j] += __shfl_xor_sync(0xffffffffu, p[j], o);

    float mx = -1e30f;
    #pragma unroll
    for (int j = 0; j < 5; j++) {
        float l = p[j] + sb[j];
        l = l > 0.f ? l : 0.01f * l;
        p[j] = l;
        mx = fmaxf(mx, l);
    }
    float se = 0.f;
    #pragma unroll
    for (int j = 0; j < 5; j++) { p[j] = __expf(p[j] - mx); se += p[j]; }
    float inv = 1.f / se;

    float2 o2 = make_float2(0.f, 0.f);
    #pragma unroll
    for (int k = 0; k < 5; k++) {
        float w = p[k] * inv;
        o2.x += w * f[k].x;
        o2.y += w * f[k].y;
    }
    ((float2*)(out + (size_t)u * LATDIM))[lane] = o2;
}

// ---------------------------------------------------------------------------

extern "C" void kernel_launch(void* const* d_in, const int* in_sizes, int n_in,
                              void* d_out, int out_size)
{
    const float* uE  = (const float*)d_in[0];
    const float* iE  = (const float*)d_in[1];
    const float* Wg  = (const float*)d_in[2];
    const float* bg  = (const float*)d_in[3];
    const float* WL1 = (const float*)d_in[4];
    const float* bL1 = (const float*)d_in[5];
    const float* WL2 = (const float*)d_in[6];
    const float* bL2 = (const float*)d_in[7];
    const int*   ir  = (const int*)d_in[8];
    const int*   ic  = (const int*)d_in[9];
    const float* iv  = (const float*)d_in[10];
    const int*   sr  = (const int*)d_in[11];
    const int*   sc  = (const int*)d_in[12];
    const float* sv  = (const float*)d_in[13];
    float* out = (float*)d_out;

    float *socB, *intU, *fuB;
    __half *combB, *socH, *it3;
    cudaGetSymbolAddress((void**)&socB,  g_soc);
    cudaGetSymbolAddress((void**)&intU,  g_interU);
    cudaGetSymbolAddress((void**)&fuB,   g_fusedU);
    cudaGetSymbolAddress((void**)&combB, g_comb);
    cudaGetSymbolAddress((void**)&socH,  g_soch);
    cudaGetSymbolAddress((void**)&it3,   g_it3);

    int *icnt, *icur, *iptr, *ibs, *scnt, *scur, *sptr, *sbs;
    int2 *icv, *scv;
    cudaGetSymbolAddress((void**)&icnt, g_icnt);
    cudaGetSymbolAddress((void**)&icur, g_icur);
    cudaGetSymbolAddress((void**)&iptr, g_iptr);
    cudaGetSymbolAddress((void**)&icv,  g_icv);
    cudaGetSymbolAddress((void**)&ibs,  g_ibsum);
    cudaGetSymbolAddress((void**)&scnt, g_scnt);
    cudaGetSymbolAddress((void**)&scur, g_scur);
    cudaGetSymbolAddress((void**)&sptr, g_sptr);
    cudaGetSymbolAddress((void**)&scv,  g_scv);
    cudaGetSymbolAddress((void**)&sbs,  g_sbsum);

    const size_t USZ = (size_t)N_USER * LATDIM;
    const size_t NSZ = (size_t)N_NODE * LATDIM;
    const int NB_I = (N_NODE + 2047) / 2048;   // 147
    const int NB_S = (N_USER + 2047) / 2048;   // 49
    const int nI2 = N_ITEM * LATDIM / 2;       // 6.4M half2

    const int GRID_U = (N_USER * 16 + 255) / 256;   // user-row spmm
    const int GRID_I = (N_ITEM * 16 + 255) / 256;   // item-row spmm

    // --- streams & events ---
    cudaStream_t s2, s3;
    cudaStreamCreateWithFlags(&s2, cudaStreamNonBlocking);
    cudaStreamCreateWithFlags(&s3, cudaStreamNonBlocking);
    cudaEvent_t evFork, evSoc[4], evGate[4], evItem[4], evMain0;
    cudaEventCreateWithFlags(&evFork, cudaEventDisableTiming);
    cudaEventCreateWithFlags(&evMain0, cudaEventDisableTiming);
    for (int k = 0; k < 4; k++) {
        cudaEventCreateWithFlags(&evSoc[k],  cudaEventDisableTiming);
        cudaEventCreateWithFlags(&evGate[k], cudaEventDisableTiming);
        cudaEventCreateWithFlags(&evItem[k], cudaEventDisableTiming);
    }

    cudaEventRecord(evFork, 0);
    cudaStreamWaitEvent(s2, evFork, 0);
    cudaStreamWaitEvent(s3, evFork, 0);

    // === s2: soc CSR build + soc chain (layers 1..4) ===
    hist_rows<<<(E_SOC + 255) / 256, 256, 0, s2>>>(sr, E_SOC, scnt);
    block_sum<<<NB_S, 256, 0, s2>>>(scnt, N_USER, sbs);
    scan_final<<<NB_S, 256, 0, s2>>>(scnt, N_USER, sbs, NB_S, sptr, scur, E_SOC);
    scatter_edges<<<(E_SOC + 255) / 256, 256, 0, s2>>>(sr, sc, sv, E_SOC, scur, scv);

    spmm_f32src<<<GRID_U, 256, 0, s2>>>(sptr, scv, uE, socB, socH, N_USER);
    cudaEventRecord(evSoc[0], s2);
    for (int k = 1; k < 4; k++) {
        spmm_f16<<<GRID_U, 256, 0, s2>>>(
            sptr, scv, socH + (size_t)(k - 1) * USZ,
            socB + (size_t)k * USZ,
            (k < 3) ? socH + (size_t)k * USZ : nullptr, 0, 0, N_USER);
        cudaEventRecord(evSoc[k], s2);
    }

    // === main: gate0 (needs only uE), then inter CSR build (+ iE fp16 conv) ===
    gate_fuse<<<(N_USER * 32 + 255) / 256, 256>>>(
        uE, uE, Wg, bg, fuB, combB);                       // comb[0] user region

    hist_rows<<<(E_INTER + 255) / 256, 256>>>(ir, E_INTER, icnt);
    block_sum<<<NB_I, 256>>>(icnt, N_NODE, ibs);
    scan_final<<<NB_I, 256>>>(icnt, N_NODE, ibs, NB_I, iptr, icur, E_INTER);
    {
        int tot = (E_INTER > nI2) ? E_INTER : nI2;
        scatter_conv<<<(tot + 255) / 256, 256>>>(ir, ic, iv, E_INTER, icur, icv,
                                                 (const float2*)iE,
                                                 (__half2*)(combB + USZ), nI2);
    }
    cudaEventRecord(evMain0, 0);   // comb[0] complete (gate0 + conv) & CSR ready

    // === layers 0..3: user-spmm on main, item-spmm on s3 ===
    for (int k = 0; k < 4; k++) {
        __half* combk = combB + (size_t)k * NSZ;

        // item rows -> comb[k+1] item region (k<3) or it3 (k=3); fp16 only
        cudaStreamWaitEvent(s3, (k == 0) ? evMain0 : evGate[k], 0);
        __half* dsth = (k < 3) ? combB + (size_t)(k + 1) * NSZ + USZ : it3;
        spmm_f16<<<GRID_I, 256, 0, s3>>>(
            iptr, icv, combk, nullptr, dsth, N_USER, N_USER, N_NODE);
        cudaEventRecord(evItem[k], s3);

        // user rows -> intU[k]; fp32 only (main)
        if (k >= 1) cudaStreamWaitEvent(0, evItem[k - 1], 0);
        spmm_f16<<<GRID_U, 256>>>(
            iptr, icv, combk, intU + (size_t)k * USZ, nullptr, 0, 0, N_USER);

        // gate_{k+1} on main (needs soc[k] + intU[k])
        cudaStreamWaitEvent(0, evSoc[k], 0);
        gate_fuse<<<(N_USER * 32 + 255) / 256, 256>>>(
            socB + (size_t)k * USZ, intU + (size_t)k * USZ,
            Wg + (k + 1) * 256, bg + (k + 1) * 2,
            fuB + (size_t)(k + 1) * USZ,
            (k < 3) ? combB + (size_t)(k + 1) * NSZ : nullptr);
        if (k < 3) cudaEventRecord(evGate[k + 1], 0);
    }

    // --- attention readouts ---
    attn5<<<(N_USER * 32 + 255) / 256, 256>>>(
        fuB, fuB + USZ, fuB + 2 * USZ, fuB + 3 * USZ, fuB + 4 * USZ,
        WL1, bL1, out, N_USER);
    cudaStreamWaitEvent(0, evItem[3], 0);
    attn5h<<<(N_ITEM * 32 + 255) / 256, 256>>>(
        iE,
        combB + 1 * NSZ + USZ, combB + 2 * NSZ + USZ, combB + 3 * NSZ + USZ, it3,
        WL2, bL2, out + USZ, N_ITEM);

    // --- cleanup ---
    cudaEventDestroy(evFork);
    cudaEventDestroy(evMain0);
    for (int k = 0; k < 4; k++) {
        cudaEventDestroy(evSoc[k]);
        cudaEventDestroy(evGate[k]);
        cudaEventDestroy(evItem[k]);
    }
    cudaStreamDestroy(s2);
    cudaStreamDestroy(s3);
}